// round 1
// baseline (speedup 1.0000x reference)
#include <cuda_runtime.h>
#include <math.h>

#define SQ 2048           // sequence length
#define NH 16             // attention heads
#define DNN 128           // nope dim
#define DRR 64            // rope dim
#define DVV 128           // v dim
#define QRR 1536
#define KRR 512
#define HII 32            // indexer heads
#define DII 128           // indexer dim
#define TOPK 512
#define DMM 2048

// ---------------- scratch (device globals; no allocation allowed) ----------
__device__ float g_qr   [SQ * QRR];            // 12.6 MB
__device__ float g_q    [SQ * NH * (DNN+DRR)]; // 25 MB   [s,16,192]
__device__ float g_kvall[SQ * (KRR + DRR)];    // 4.7 MB  [s,576]
__device__ float g_kv   [SQ * KRR];            // 4.2 MB
__device__ float g_kvp  [SQ * NH * (DNN+DVV)]; // 33.5 MB [s,16,256]
__device__ float g_k    [SQ * NH * (DNN+DRR)]; // 25 MB   [s,16,192]
__device__ float g_qi   [SQ * HII * DII];      // 33.5 MB [s,32,128]
__device__ float g_ki   [SQ * DII];            // 1 MB
__device__ float g_wts  [SQ * HII];            // 0.26 MB
__device__ float g_iscore[SQ * SQ];            // 16.8 MB
__device__ float g_comb [SQ * SQ];             // 16.8 MB (0 if selected & causal, else -inf)
__device__ float g_scores[67108864];           // 268 MB  [16, s, t]
__device__ float g_attnout[SQ * DMM];          // 16.8 MB

#define NEG_INF (__int_as_float(0xff800000))

// ---------------- generic C = alpha * A @ B^T, optional batch + causal -----
// A: M x K (row stride lda), B: N x K (row stride ldb), C: M x N (ldc)
__global__ __launch_bounds__(256) void gemm_nt_k(
    const float* __restrict__ A, long sa, int lda,
    const float* __restrict__ B, long sb, int ldb,
    float* __restrict__ C, long sc, int ldc,
    int M, int N, int K, float alpha, int causal)
{
    int bz = blockIdx.z;
    A += (long)bz * sa; B += (long)bz * sb; C += (long)bz * sc;
    int n0 = blockIdx.x * 64, m0 = blockIdx.y * 64;
    if (causal && n0 > m0 + 63) return;

    __shared__ float As[16][64];
    __shared__ float Bs[16][64];
    int tx = threadIdx.x, ty = threadIdx.y;
    int tid = ty * 16 + tx;
    int lr = tid >> 2;           // 0..63
    int lc = (tid & 3) * 4;      // 0,4,8,12

    float acc[4][4] = {};
    for (int k0 = 0; k0 < K; k0 += 16) {
        // A tile (K is always a multiple of 16 in this problem)
        if (m0 + lr < M) {
            float4 v = *(const float4*)(A + (long)(m0 + lr) * lda + k0 + lc);
            As[lc][lr] = v.x; As[lc+1][lr] = v.y; As[lc+2][lr] = v.z; As[lc+3][lr] = v.w;
        } else {
            As[lc][lr] = 0.f; As[lc+1][lr] = 0.f; As[lc+2][lr] = 0.f; As[lc+3][lr] = 0.f;
        }
        if (n0 + lr < N) {
            float4 v = *(const float4*)(B + (long)(n0 + lr) * ldb + k0 + lc);
            Bs[lc][lr] = v.x; Bs[lc+1][lr] = v.y; Bs[lc+2][lr] = v.z; Bs[lc+3][lr] = v.w;
        } else {
            Bs[lc][lr] = 0.f; Bs[lc+1][lr] = 0.f; Bs[lc+2][lr] = 0.f; Bs[lc+3][lr] = 0.f;
        }
        __syncthreads();
        #pragma unroll
        for (int k = 0; k < 16; k++) {
            float4 a4 = *(const float4*)(&As[k][ty * 4]);
            float4 b4 = *(const float4*)(&Bs[k][tx * 4]);
            float a[4] = {a4.x, a4.y, a4.z, a4.w};
            float b[4] = {b4.x, b4.y, b4.z, b4.w};
            #pragma unroll
            for (int i = 0; i < 4; i++)
                #pragma unroll
                for (int j = 0; j < 4; j++)
                    acc[i][j] += a[i] * b[j];
        }
        __syncthreads();
    }
    #pragma unroll
    for (int i = 0; i < 4; i++) {
        int m = m0 + ty * 4 + i;
        if (m >= M) continue;
        #pragma unroll
        for (int j = 0; j < 4; j++) {
            int n = n0 + tx * 4 + j;
            if (n < N) C[(long)m * ldc + n] = alpha * acc[i][j];
        }
    }
}

// ---------------- rmsnorm (per row) ----------------------------------------
__global__ void rmsnorm_k(const float* __restrict__ in, int ldi,
                          float* __restrict__ out, int ldo,
                          const float* __restrict__ w, int D)
{
    int s = blockIdx.x, tid = threadIdx.x;
    __shared__ float red[256];
    const float* ip = in + (long)s * ldi;
    float ss = 0.f;
    for (int d = tid; d < D; d += 256) { float v = ip[d]; ss += v * v; }
    red[tid] = ss; __syncthreads();
    for (int o = 128; o > 0; o >>= 1) { if (tid < o) red[tid] += red[tid + o]; __syncthreads(); }
    float scale = rsqrtf(red[0] / (float)D + 1e-6f);
    float* op = out + (long)s * ldo;
    for (int d = tid; d < D; d += 256) op[d] = ip[d] * scale * w[d];
}

// ---------------- rope (interleaved) on q's last 64 dims, in-place --------
__global__ void rope_q_k(float* __restrict__ q,
                         const float* __restrict__ cs, const float* __restrict__ sn)
{
    int s = blockIdx.x;
    int tid = threadIdx.x;       // 512 = 16 heads * 32 pairs
    int h = tid >> 5, i = tid & 31;
    float c = cs[s * 32 + i], si = sn[s * 32 + i];
    float* p = q + (long)s * 3072 + h * 192 + 128 + 2 * i;
    float x0 = p[0], x1 = p[1];
    p[0] = x0 * c - x1 * si;
    p[1] = x0 * si + x1 * c;
}

// ---------------- assemble k = [kvp[...,:128], rope(k_pe)] -----------------
__global__ void build_k_k(const float* __restrict__ kvp, const float* __restrict__ kvall,
                          float* __restrict__ kk,
                          const float* __restrict__ cs, const float* __restrict__ sn)
{
    int s = blockIdx.x, h = blockIdx.y;
    int tid = threadIdx.x;       // 128
    float* dst = kk + ((long)s * 16 + h) * 192;
    dst[tid] = kvp[(long)s * 4096 + h * 256 + tid];
    if (tid < 32) {
        float c = cs[s * 32 + tid], si = sn[s * 32 + tid];
        float x0 = kvall[(long)s * 576 + 512 + 2 * tid];
        float x1 = kvall[(long)s * 576 + 513 + 2 * tid];
        dst[128 + 2 * tid] = x0 * c - x1 * si;
        dst[129 + 2 * tid] = x0 * si + x1 * c;
    }
}

// ---------------- rope_half on qi first 64 dims per head, in-place --------
__global__ void rope_qi_k(float* __restrict__ qi,
                          const float* __restrict__ cs, const float* __restrict__ sn)
{
    int s = blockIdx.x;
    int tid = threadIdx.x;       // 1024 = 32 heads * 32 dims
    int h = tid >> 5, d = tid & 31;
    float c = cs[s * 32 + d], si = sn[s * 32 + d];
    float* p = qi + (long)s * 4096 + h * 128;
    float x0 = p[d], x1 = p[d + 32];
    p[d] = x0 * c - x1 * si;
    p[d + 32] = x0 * si + x1 * c;
}

// ---------------- layernorm + rope_half for ki (in-place, width 128) ------
__global__ void ln_rope_ki_k(float* __restrict__ ki,
                             const float* __restrict__ w, const float* __restrict__ b,
                             const float* __restrict__ cs, const float* __restrict__ sn)
{
    int s = blockIdx.x, tid = threadIdx.x;   // 128
    __shared__ float red[128];
    __shared__ float buf[128];
    float v = ki[(long)s * 128 + tid];
    red[tid] = v; __syncthreads();
    for (int o = 64; o > 0; o >>= 1) { if (tid < o) red[tid] += red[tid + o]; __syncthreads(); }
    float mean = red[0] / 128.f; __syncthreads();
    float d = v - mean;
    red[tid] = d * d; __syncthreads();
    for (int o = 64; o > 0; o >>= 1) { if (tid < o) red[tid] += red[tid + o]; __syncthreads(); }
    float var = red[0] / 128.f;
    float nv = d * rsqrtf(var + 1e-5f) * w[tid] + b[tid];
    buf[tid] = nv; __syncthreads();
    float out;
    if (tid < 32) {
        float c = cs[s * 32 + tid], si = sn[s * 32 + tid];
        out = buf[tid] * c - buf[tid + 32] * si;
    } else if (tid < 64) {
        int i = tid - 32;
        float c = cs[s * 32 + i], si = sn[s * 32 + i];
        out = buf[i] * si + buf[i + 32] * c;
    } else {
        out = nv;
    }
    ki[(long)s * 128 + tid] = out;
}

// ---------------- indexer scores: sum_h relu(qi_h . ki / sqrt(128)) * w ---
__global__ __launch_bounds__(256) void indexer_k(
    const float* __restrict__ qi, const float* __restrict__ ki,
    const float* __restrict__ wts, float* __restrict__ out)
{
    int t0 = blockIdx.x * 64, s0 = blockIdx.y * 64;
    if (t0 > s0 + 63) return;   // purely above diagonal: never read
    __shared__ float Bs[128][64];   // ki[k][t]
    __shared__ float As[16][64];    // qi chunk [k][s]
    __shared__ float Ws[2048];      // wts [64 s][32 h]
    int tx = threadIdx.x, ty = threadIdx.y;
    int tid = ty * 16 + tx;
    {
        int r = tid >> 2, c0 = (tid & 3) * 32;
        const float* kp = ki + (long)(t0 + r) * 128 + c0;
        #pragma unroll
        for (int c = 0; c < 32; c += 4) {
            float4 v = *(const float4*)(kp + c);
            Bs[c0+c][r] = v.x; Bs[c0+c+1][r] = v.y; Bs[c0+c+2][r] = v.z; Bs[c0+c+3][r] = v.w;
        }
    }
    for (int i = tid; i < 2048; i += 256)
        Ws[i] = wts[(long)(s0 + (i >> 5)) * 32 + (i & 31)];
    __syncthreads();

    const float scl = 0.08838834764831845f;  // 1/sqrt(128)
    float fin[4][4] = {};
    int lr = tid >> 2, lc = (tid & 3) * 4;
    for (int h = 0; h < 32; h++) {
        float acc[4][4] = {};
        for (int kk = 0; kk < 128; kk += 16) {
            float4 v = *(const float4*)(qi + (long)(s0 + lr) * 4096 + h * 128 + kk + lc);
            As[lc][lr] = v.x; As[lc+1][lr] = v.y; As[lc+2][lr] = v.z; As[lc+3][lr] = v.w;
            __syncthreads();
            #pragma unroll
            for (int k = 0; k < 16; k++) {
                float4 a4 = *(const float4*)(&As[k][ty * 4]);
                float4 b4 = *(const float4*)(&Bs[kk + k][tx * 4]);
                float a[4] = {a4.x, a4.y, a4.z, a4.w};
                float b[4] = {b4.x, b4.y, b4.z, b4.w};
                #pragma unroll
                for (int i = 0; i < 4; i++)
                    #pragma unroll
                    for (int j = 0; j < 4; j++)
                        acc[i][j] += a[i] * b[j];
            }
            __syncthreads();
        }
        #pragma unroll
        for (int i = 0; i < 4; i++) {
            float wv = Ws[(ty * 4 + i) * 32 + h];
            #pragma unroll
            for (int j = 0; j < 4; j++)
                fin[i][j] += fmaxf(acc[i][j] * scl, 0.f) * wv;
        }
    }
    #pragma unroll
    for (int i = 0; i < 4; i++)
        #pragma unroll
        for (int j = 0; j < 4; j++)
            out[(long)(s0 + ty * 4 + i) * SQ + t0 + tx * 4 + j] = fin[i][j];
}

// ---------------- per-row top-512 -> combined mask (0 keep / -inf drop) ---
__global__ __launch_bounds__(1024) void topk_mask_k(
    const float* __restrict__ iscore, float* __restrict__ comb)
{
    int s = blockIdx.x, tid = threadIdx.x;
    __shared__ float sv[2048];
    __shared__ float xo[2048];
    __shared__ unsigned char sel[2048];
    __shared__ int s_cnt;
    for (int t = tid; t < 2048; t += 1024) {
        float v = (t <= s) ? iscore[(long)s * SQ + t] : NEG_INF;
        xo[t] = v; sv[t] = v; sel[t] = 0;
    }
    if (tid == 0) s_cnt = 0;
    __syncthreads();

    if (s <= TOPK - 1) {  // <=512 causal entries: keep all
        for (int t = tid; t < 2048; t += 1024)
            comb[(long)s * SQ + t] = (t <= s) ? 0.f : NEG_INF;
        return;
    }
    // bitonic sort ascending (2048 elements, 1024 threads)
    for (int k = 2; k <= 2048; k <<= 1) {
        for (int j = k >> 1; j > 0; j >>= 1) {
            for (int t = tid; t < 2048; t += 1024) {
                int ixj = t ^ j;
                if (ixj > t) {
                    float a = sv[t], b = sv[ixj];
                    bool asc = ((t & k) == 0);
                    if (asc ? (a > b) : (a < b)) { sv[t] = b; sv[ixj] = a; }
                }
            }
            __syncthreads();
        }
    }
    float T = sv[2048 - TOPK];   // 512th largest
    int local = 0;
    for (int t = tid; t <= s; t += 1024)
        if (xo[t] > T) { sel[t] = 1; local++; }
    atomicAdd(&s_cnt, local);
    __syncthreads();
    if (tid == 0) {
        int quota = TOPK - s_cnt;    // fill ties at T by lowest index (jax tie-break)
        for (int t = 0; t <= s && quota > 0; t++)
            if (!sel[t] && xo[t] == T) { sel[t] = 1; quota--; }
    }
    __syncthreads();
    for (int t = tid; t < 2048; t += 1024)
        comb[(long)s * SQ + t] = sel[t] ? 0.f : NEG_INF;
}

// ---------------- masked softmax over t, in-place on g_scores --------------
__global__ void softmax_k(float* __restrict__ scores, const float* __restrict__ comb)
{
    int s = blockIdx.x, h = blockIdx.y, tid = threadIdx.x;
    float* row = scores + ((long)h * SQ + s) * SQ;
    const float* cm = comb + (long)s * SQ;
    __shared__ float red[256];
    float m = NEG_INF;
    for (int t = tid; t < SQ; t += 256)
        if (cm[t] == 0.f) m = fmaxf(m, row[t]);
    red[tid] = m; __syncthreads();
    for (int o = 128; o > 0; o >>= 1) { if (tid < o) red[tid] = fmaxf(red[tid], red[tid + o]); __syncthreads(); }
    m = red[0]; __syncthreads();
    float sum = 0.f;
    for (int t = tid; t < SQ; t += 256) {
        float e = (cm[t] == 0.f) ? expf(row[t] - m) : 0.f;
        row[t] = e; sum += e;
    }
    red[tid] = sum; __syncthreads();
    for (int o = 128; o > 0; o >>= 1) { if (tid < o) red[tid] += red[tid + o]; __syncthreads(); }
    float inv = 1.f / red[0];
    for (int t = tid; t < SQ; t += 256) row[t] *= inv;
}

// ---------------- out[.,h,:] = probs_h @ v_h  (NN GEMM, causal K-bound) ----
__global__ __launch_bounds__(256) void pv_gemm_k(
    const float* __restrict__ probs, const float* __restrict__ kvp,
    float* __restrict__ out)
{
    int h = blockIdx.z;
    const float* A = probs + (long)h * SQ * SQ;   // lda = SQ
    const float* B = kvp + h * 256 + 128;         // ldb = 4096
    float* C = out + h * 128;                     // ldc = 2048
    int n0 = blockIdx.x * 64, m0 = blockIdx.y * 64;
    int Kmax = m0 + 64;                           // probs zero beyond diagonal
    __shared__ float As[16][64];
    __shared__ float Bs[16][64];
    int tx = threadIdx.x, ty = threadIdx.y;
    int tid = ty * 16 + tx;
    int ar = tid >> 2, ac = (tid & 3) * 4;        // A: 64 rows x 16 k
    int br = tid >> 4, bc = (tid & 15) * 4;       // B: 16 k x 64 n
    float acc[4][4] = {};
    for (int k0 = 0; k0 < Kmax; k0 += 16) {
        float4 va = *(const float4*)(A + (long)(m0 + ar) * SQ + k0 + ac);
        As[ac][ar] = va.x; As[ac+1][ar] = va.y; As[ac+2][ar] = va.z; As[ac+3][ar] = va.w;
        float4 vb = *(const float4*)(B + (long)(k0 + br) * 4096 + n0 + bc);
        Bs[br][bc] = vb.x; Bs[br][bc+1] = vb.y; Bs[br][bc+2] = vb.z; Bs[br][bc+3] = vb.w;
        __syncthreads();
        #pragma unroll
        for (int k = 0; k < 16; k++) {
            float4 a4 = *(const float4*)(&As[k][ty * 4]);
            float4 b4 = *(const float4*)(&Bs[k][tx * 4]);
            float a[4] = {a4.x, a4.y, a4.z, a4.w};
            float b[4] = {b4.x, b4.y, b4.z, b4.w};
            #pragma unroll
            for (int i = 0; i < 4; i++)
                #pragma unroll
                for (int j = 0; j < 4; j++)
                    acc[i][j] += a[i] * b[j];
        }
        __syncthreads();
    }
    #pragma unroll
    for (int i = 0; i < 4; i++)
        #pragma unroll
        for (int j = 0; j < 4; j++)
            C[(long)(m0 + ty * 4 + i) * 2048 + n0 + tx * 4 + j] = acc[i][j];
}

// ---------------- host orchestration ---------------------------------------
extern "C" void kernel_launch(void* const* d_in, const int* in_sizes, int n_in,
                              void* d_out, int out_size)
{
    if (n_in < 16) return;
    const float *hidden, *wq_a, *q_norm_w, *wq_b, *wkv_a, *kv_norm_w, *wkv_b, *wo;
    const float *idx_wq_b, *idx_wk, *idx_kn_w, *idx_kn_b, *idx_wproj, *fcos, *fsin;
    if (in_sizes[1] == 1536 * 2048) {
        // setup_inputs dict order
        hidden   = (const float*)d_in[0];  wq_a     = (const float*)d_in[1];
        q_norm_w = (const float*)d_in[2];  wq_b     = (const float*)d_in[3];
        wkv_a    = (const float*)d_in[4];  kv_norm_w= (const float*)d_in[5];
        wkv_b    = (const float*)d_in[6];  wo       = (const float*)d_in[7];
        idx_wq_b = (const float*)d_in[8];  idx_wk   = (const float*)d_in[9];
        idx_kn_w = (const float*)d_in[10]; idx_kn_b = (const float*)d_in[11];
        idx_wproj= (const float*)d_in[12]; fcos     = (const float*)d_in[13];
        fsin     = (const float*)d_in[14];
    } else {
        // reference() signature order (mask at index 3, unused — recomputed)
        hidden   = (const float*)d_in[0];  fcos     = (const float*)d_in[1];
        fsin     = (const float*)d_in[2];
        wq_a     = (const float*)d_in[4];  q_norm_w = (const float*)d_in[5];
        wq_b     = (const float*)d_in[6];  wkv_a    = (const float*)d_in[7];
        kv_norm_w= (const float*)d_in[8];  wkv_b    = (const float*)d_in[9];
        wo       = (const float*)d_in[10]; idx_wq_b = (const float*)d_in[11];
        idx_wk   = (const float*)d_in[12]; idx_kn_w = (const float*)d_in[13];
        idx_kn_b = (const float*)d_in[14]; idx_wproj= (const float*)d_in[15];
    }

    float *qr, *q, *kvall, *kv, *kvp, *k, *qi, *ki, *wts, *iscore, *comb, *scores, *attnout;
    cudaGetSymbolAddress((void**)&qr, g_qr);
    cudaGetSymbolAddress((void**)&q, g_q);
    cudaGetSymbolAddress((void**)&kvall, g_kvall);
    cudaGetSymbolAddress((void**)&kv, g_kv);
    cudaGetSymbolAddress((void**)&kvp, g_kvp);
    cudaGetSymbolAddress((void**)&k, g_k);
    cudaGetSymbolAddress((void**)&qi, g_qi);
    cudaGetSymbolAddress((void**)&ki, g_ki);
    cudaGetSymbolAddress((void**)&wts, g_wts);
    cudaGetSymbolAddress((void**)&iscore, g_iscore);
    cudaGetSymbolAddress((void**)&comb, g_comb);
    cudaGetSymbolAddress((void**)&scores, g_scores);
    cudaGetSymbolAddress((void**)&attnout, g_attnout);
    float* outp = (float*)d_out;

    dim3 blk(16, 16);
    const float inv_sqrt192 = 0.07216878364870323f;
    const float inv_sqrt32  = 0.17677669529663687f;

    // 1) qr_pre = hidden @ wq_a^T
    gemm_nt_k<<<dim3(QRR/64, SQ/64, 1), blk>>>(hidden, 0, DMM, wq_a, 0, DMM, qr, 0, QRR,
                                               SQ, QRR, DMM, 1.f, 0);
    // 2) rmsnorm qr (in place)
    rmsnorm_k<<<SQ, 256>>>(qr, QRR, qr, QRR, q_norm_w, QRR);
    // 3) q = qr @ wq_b^T
    gemm_nt_k<<<dim3(3072/64, SQ/64, 1), blk>>>(qr, 0, QRR, wq_b, 0, QRR, q, 0, 3072,
                                                SQ, 3072, QRR, 1.f, 0);
    // 4) kv_all = hidden @ wkv_a^T
    gemm_nt_k<<<dim3(9, SQ/64, 1), blk>>>(hidden, 0, DMM, wkv_a, 0, DMM, kvall, 0, 576,
                                          SQ, 576, DMM, 1.f, 0);
    // 5) kv = rmsnorm(kv_all[:, :512])
    rmsnorm_k<<<SQ, 256>>>(kvall, 576, kv, KRR, kv_norm_w, KRR);
    // 6) kvp = kv @ wkv_b^T
    gemm_nt_k<<<dim3(4096/64, SQ/64, 1), blk>>>(kv, 0, KRR, wkv_b, 0, KRR, kvp, 0, 4096,
                                                SQ, 4096, KRR, 1.f, 0);
    // 7) rope q (in place)
    rope_q_k<<<SQ, 512>>>(q, fcos, fsin);
    // 8) assemble k
    build_k_k<<<dim3(SQ, NH), 128>>>(kvp, kvall, k, fcos, fsin);
    // 9) qi = qr @ idx_wq_b^T
    gemm_nt_k<<<dim3(4096/64, SQ/64, 1), blk>>>(qr, 0, QRR, idx_wq_b, 0, QRR, qi, 0, 4096,
                                                SQ, 4096, QRR, 1.f, 0);
    // 10) rope_half qi (in place)
    rope_qi_k<<<SQ, 1024>>>(qi, fcos, fsin);
    // 11) ki = hidden @ idx_wk^T
    gemm_nt_k<<<dim3(2, SQ/64, 1), blk>>>(hidden, 0, DMM, idx_wk, 0, DMM, ki, 0, DII,
                                          SQ, DII, DMM, 1.f, 0);
    // 12) layernorm + rope_half ki (in place)
    ln_rope_ki_k<<<SQ, 128>>>(ki, idx_kn_w, idx_kn_b, fcos, fsin);
    // 13) wts = hidden @ idx_wproj^T * HI^-0.5
    gemm_nt_k<<<dim3(1, SQ/64, 1), blk>>>(hidden, 0, DMM, idx_wproj, 0, DMM, wts, 0, HII,
                                          SQ, HII, DMM, inv_sqrt32, 0);
    // 14) indexer scores
    indexer_k<<<dim3(SQ/64, SQ/64), blk>>>(qi, ki, wts, iscore);
    // 15) top-512 -> combined mask
    topk_mask_k<<<SQ, 1024>>>(iscore, comb);
    // 16) attention scores per head (causal)
    gemm_nt_k<<<dim3(SQ/64, SQ/64, NH), blk>>>(q, 192, 3072, k, 192, 3072,
                                               scores, (long)SQ * SQ, SQ,
                                               SQ, SQ, 192, inv_sqrt192, 1);
    // 17) masked softmax
    softmax_k<<<dim3(SQ, NH), 256>>>(scores, comb);
    // 18) attn_out = probs @ v
    pv_gemm_k<<<dim3(2, SQ/64, NH), blk>>>(scores, kvp, attnout);
    // 19) out = attn_out @ wo^T
    gemm_nt_k<<<dim3(DMM/64, SQ/64, 1), blk>>>(attnout, 0, DMM, wo, 0, DMM, outp, 0, DMM,
                                               SQ, DMM, DMM, 1.f, 0);
}